// round 1
// baseline (speedup 1.0000x reference)
#include <cuda_runtime.h>
#include <string.h>

#define T_LEN 256
#define HID   20
#define GATES 80   // 4*HID
#define GP    40   // gate pairs
#define FFD   64

// ---------- packed fp32x2 FMA (sm_103a; PTX-only path) ----------
union F2U { float2 f; unsigned long long u; };

__device__ __forceinline__ float2 ffma2(float2 a, float2 b, float2 c) {
    F2U A, B, C, D;
    A.f = a; B.f = b; C.f = c;
    asm("fma.rn.f32x2 %0, %1, %2, %3;" : "=l"(D.u) : "l"(A.u), "l"(B.u), "l"(C.u));
    return D.f;
}

__device__ __forceinline__ float fast_ex2(float x) {
    float r; asm("ex2.approx.f32 %0, %1;" : "=f"(r) : "f"(x)); return r;
}
__device__ __forceinline__ float fast_rcp(float x) {
    float r; asm("rcp.approx.f32 %0, %1;" : "=f"(r) : "f"(x)); return r;
}
// sigmoid(x) = 1/(1+2^(-x*log2e))
__device__ __forceinline__ float sigm(float x) {
    return fast_rcp(1.0f + fast_ex2(-1.4426950408889634f * x));
}
// tanh(x) = 1 - 2/(1+2^(2x*log2e))
__device__ __forceinline__ float tanh_f(float x) {
    return fmaf(-2.0f, fast_rcp(1.0f + fast_ex2(2.8853900817779268f * x)), 1.0f);
}

__device__ __forceinline__ float half_of(const float2* v, int k) {
    return (k & 1) ? v[k >> 1].y : v[k >> 1].x;
}

// One fused 2-layer LSTM timestep for one row. All loops fully unrolled
// (register-resident state requires static indexing).
__device__ __forceinline__ void lstm_step(
    float x,
    float2* h1, float2* c1, float2* h2, float2* c2,
    const float2* s_wih1, const float2* s_b1,
    const float4* s_w1,   const float4* s_w2, const float2* s_b2)
{
    float2 z[GP];
    const float2 xx = make_float2(x, x);

    // ---- layer 1: z = b + x*W_ih1 + W_hh1 @ h1 ----
#pragma unroll
    for (int jp = 0; jp < GP; jp++) z[jp] = ffma2(s_wih1[jp], xx, s_b1[jp]);

#pragma unroll
    for (int k = 0; k < HID; k++) {
        float hk = half_of(h1, k);
        float2 hh = make_float2(hk, hk);
#pragma unroll
        for (int q = 0; q < GP / 2; q++) {
            float4 w = s_w1[k * (GP / 2) + q];
            z[2 * q]     = ffma2(make_float2(w.x, w.y), hh, z[2 * q]);
            z[2 * q + 1] = ffma2(make_float2(w.z, w.w), hh, z[2 * q + 1]);
        }
    }
#pragma unroll
    for (int m = 0; m < HID / 2; m++) {
        float2 zi = z[m], zf = z[10 + m], zg = z[20 + m], zo = z[30 + m];
        float i0 = sigm(zi.x),  i1 = sigm(zi.y);
        float f0 = sigm(zf.x),  f1 = sigm(zf.y);
        float g0 = tanh_f(zg.x), g1 = tanh_f(zg.y);
        float o0 = sigm(zo.x),  o1 = sigm(zo.y);
        float cc0 = fmaf(f0, c1[m].x, i0 * g0);
        float cc1 = fmaf(f1, c1[m].y, i1 * g1);
        c1[m] = make_float2(cc0, cc1);
        h1[m] = make_float2(o0 * tanh_f(cc0), o1 * tanh_f(cc1));
    }

    // ---- layer 2: z = b + W_ih2 @ h1_new + W_hh2 @ h2 ----
#pragma unroll
    for (int jp = 0; jp < GP; jp++) z[jp] = s_b2[jp];

#pragma unroll
    for (int k = 0; k < 2 * HID; k++) {
        float hk = (k < HID) ? half_of(h1, k) : half_of(h2, k - HID);
        float2 hh = make_float2(hk, hk);
#pragma unroll
        for (int q = 0; q < GP / 2; q++) {
            float4 w = s_w2[k * (GP / 2) + q];
            z[2 * q]     = ffma2(make_float2(w.x, w.y), hh, z[2 * q]);
            z[2 * q + 1] = ffma2(make_float2(w.z, w.w), hh, z[2 * q + 1]);
        }
    }
#pragma unroll
    for (int m = 0; m < HID / 2; m++) {
        float2 zi = z[m], zf = z[10 + m], zg = z[20 + m], zo = z[30 + m];
        float i0 = sigm(zi.x),  i1 = sigm(zi.y);
        float f0 = sigm(zf.x),  f1 = sigm(zf.y);
        float g0 = tanh_f(zg.x), g1 = tanh_f(zg.y);
        float o0 = sigm(zo.x),  o1 = sigm(zo.y);
        float cc0 = fmaf(f0, c2[m].x, i0 * g0);
        float cc1 = fmaf(f1, c2[m].y, i1 * g1);
        c2[m] = make_float2(cc0, cc1);
        h2[m] = make_float2(o0 * tanh_f(cc0), o1 * tanh_f(cc1));
    }
}

__global__ void __launch_bounds__(128, 2) lstm2_head_kernel(
    const float* __restrict__ diag,
    const float* __restrict__ W_ih1, const float* __restrict__ W_hh1,
    const float* __restrict__ b_ih1, const float* __restrict__ b_hh1,
    const float* __restrict__ W_ih2, const float* __restrict__ W_hh2,
    const float* __restrict__ b_ih2, const float* __restrict__ b_hh2,
    const float* __restrict__ W1,   const float* __restrict__ b1,
    const float* __restrict__ W2,   const float* __restrict__ b2,
    float* __restrict__ out, int rows)
{
    // ---------------- shared weight staging (transposed + paired) ----------------
    __shared__ float2 s_wih1[GP];          // W_ih1[2p], W_ih1[2p+1]
    __shared__ float2 s_b1[GP];            // (b_ih1+b_hh1) pairs
    __shared__ float4 s_w1[HID * (GP/2)];  // [k][q] = W_hh1[4q..4q+3][k]
    __shared__ float4 s_w2[2*HID * (GP/2)];// rows 0..19: W_ih2^T, 20..39: W_hh2^T
    __shared__ float2 s_b2[GP];            // (b_ih2+b_hh2) pairs
    __shared__ float  s_W1f[FFD * HID];    // W1 row-major
    __shared__ float  s_b1f[FFD];
    __shared__ float  s_W2f[FFD];
    __shared__ float  s_b2f;

    const int tid = threadIdx.x;
    const int bd  = blockDim.x;

    for (int i = tid; i < GP; i += bd) {
        s_wih1[i] = make_float2(W_ih1[2*i], W_ih1[2*i + 1]);
        s_b1[i]   = make_float2(b_ih1[2*i] + b_hh1[2*i], b_ih1[2*i+1] + b_hh1[2*i+1]);
        s_b2[i]   = make_float2(b_ih2[2*i] + b_hh2[2*i], b_ih2[2*i+1] + b_hh2[2*i+1]);
    }
    for (int i = tid; i < HID * (GP/2); i += bd) {
        int k = i / (GP/2), q = i % (GP/2);
        s_w1[i] = make_float4(W_hh1[(4*q + 0) * HID + k],
                              W_hh1[(4*q + 1) * HID + k],
                              W_hh1[(4*q + 2) * HID + k],
                              W_hh1[(4*q + 3) * HID + k]);
    }
    for (int i = tid; i < 2*HID * (GP/2); i += bd) {
        int k = i / (GP/2), q = i % (GP/2);
        const float* Wm = (k < HID) ? W_ih2 : W_hh2;
        int kk = (k < HID) ? k : (k - HID);
        s_w2[i] = make_float4(Wm[(4*q + 0) * HID + kk],
                              Wm[(4*q + 1) * HID + kk],
                              Wm[(4*q + 2) * HID + kk],
                              Wm[(4*q + 3) * HID + kk]);
    }
    for (int i = tid; i < FFD * HID; i += bd) s_W1f[i] = W1[i];
    for (int i = tid; i < FFD; i += bd) { s_b1f[i] = b1[i]; s_W2f[i] = W2[i]; }
    if (tid == 0) s_b2f = b2[0];
    __syncthreads();

    const int b = blockIdx.x * bd + tid;
    if (b >= rows) return;

    // ---------------- register-resident state ----------------
    float2 h1[HID/2], c1[HID/2], h2[HID/2], c2[HID/2];
#pragma unroll
    for (int m = 0; m < HID/2; m++) {
        h1[m] = make_float2(0.f, 0.f); c1[m] = make_float2(0.f, 0.f);
        h2[m] = make_float2(0.f, 0.f); c2[m] = make_float2(0.f, 0.f);
    }

    const float* __restrict__ xrow = diag + (size_t)b * T_LEN;

#pragma unroll 1
    for (int t = 0; t < T_LEN; t++) {
        float x = __ldg(xrow + t);
        lstm_step(x, h1, c1, h2, c2, s_wih1, s_b1, s_w1, s_w2, s_b2);
    }

    // ---------------- head: relu(relu(h2 @ W1^T + b1) @ W2^T + b2) ----------------
    float acc2 = s_b2f;
#pragma unroll 1
    for (int n = 0; n < FFD; n++) {
        float a = s_b1f[n];
#pragma unroll
        for (int k = 0; k < HID; k++)
            a = fmaf(s_W1f[n * HID + k], half_of(h2, k), a);
        a = fmaxf(a, 0.0f);
        acc2 = fmaf(s_W2f[n], a, acc2);
    }
    out[b] = fmaxf(acc2, 0.0f);
}

extern "C" void kernel_launch(void* const* d_in, const int* in_sizes, int n_in,
                              void* d_out, int out_size) {
    const float* diag  = (const float*)d_in[0];
    const float* W_ih1 = (const float*)d_in[1];
    const float* W_hh1 = (const float*)d_in[2];
    const float* b_ih1 = (const float*)d_in[3];
    const float* b_hh1 = (const float*)d_in[4];
    const float* W_ih2 = (const float*)d_in[5];
    const float* W_hh2 = (const float*)d_in[6];
    const float* b_ih2 = (const float*)d_in[7];
    const float* b_hh2 = (const float*)d_in[8];
    const float* W1    = (const float*)d_in[9];
    const float* b1    = (const float*)d_in[10];
    const float* W2    = (const float*)d_in[11];
    const float* b2    = (const float*)d_in[12];

    int rows = out_size;  // B = 131072 (one output per row)
    int threads = 128;
    int blocks = (rows + threads - 1) / threads;

    lstm2_head_kernel<<<blocks, threads>>>(
        diag, W_ih1, W_hh1, b_ih1, b_hh1,
        W_ih2, W_hh2, b_ih2, b_hh2,
        W1, b1, W2, b2, (float*)d_out, rows);
}

// round 2
// speedup vs baseline: 1.0744x; 1.0744x over previous
#include <cuda_runtime.h>

#define T_LEN 256
#define HID   20
#define FFD   64

// ---------- packed fp32x2 FMA (sm_103a; PTX-only path) ----------
union F2U { float2 f; unsigned long long u; };

__device__ __forceinline__ float2 ffma2(float2 a, float2 b, float2 c) {
    F2U A, B, C, D;
    A.f = a; B.f = b; C.f = c;
    asm("fma.rn.f32x2 %0, %1, %2, %3;" : "=l"(D.u) : "l"(A.u), "l"(B.u), "l"(C.u));
    return D.f;
}

__device__ __forceinline__ float tanhap(float x) {
    float r; asm("tanh.approx.f32 %0, %1;" : "=f"(r) : "f"(x)); return r;
}
// sigmoid(x) = 0.5 * tanh(x/2) + 0.5
__device__ __forceinline__ float sigm(float x) {
    return fmaf(0.5f, tanhap(0.5f * x), 0.5f);
}

__global__ void __launch_bounds__(128, 3) lstm2_head_kernel(
    const float* __restrict__ diag,
    const float* __restrict__ W_ih1, const float* __restrict__ W_hh1,
    const float* __restrict__ b_ih1, const float* __restrict__ b_hh1,
    const float* __restrict__ W_ih2, const float* __restrict__ W_hh2,
    const float* __restrict__ b_ih2, const float* __restrict__ b_hh2,
    const float* __restrict__ W1,   const float* __restrict__ b1,
    const float* __restrict__ W2,   const float* __restrict__ b2,
    float* __restrict__ out, int rows)
{
    // Gate-quad weight layout: s_w[j][k] = (Wi[j][k], Wf[j][k], Wg[j][k], Wo[j][k])
    __shared__ float4 s_w1[HID][HID];       // layer1 recurrent  (6.4 KB)
    __shared__ float4 s_w2[HID][2 * HID];   // layer2 [h1new | h2old] (12.8 KB)
    __shared__ float4 s_wx1[HID];           // layer1 input weights (in_dim=1)
    __shared__ float4 s_bq1[HID];           // summed biases, quad layout
    __shared__ float4 s_bq2[HID];
    __shared__ float  s_W1f[FFD * HID];
    __shared__ float  s_b1f[FFD];
    __shared__ float  s_W2f[FFD];
    __shared__ float  s_b2f;

    const int tid = threadIdx.x;
    const int bd  = blockDim.x;

    for (int idx = tid; idx < HID * HID; idx += bd) {
        int j = idx / HID, k = idx % HID;
        s_w1[j][k] = make_float4(W_hh1[(j      ) * HID + k],
                                 W_hh1[(HID + j) * HID + k],
                                 W_hh1[(2*HID+j) * HID + k],
                                 W_hh1[(3*HID+j) * HID + k]);
    }
    for (int idx = tid; idx < HID * 2 * HID; idx += bd) {
        int j = idx / (2 * HID), k = idx % (2 * HID);
        const float* Wm = (k < HID) ? W_ih2 : W_hh2;
        int kk = (k < HID) ? k : (k - HID);
        s_w2[j][k] = make_float4(Wm[(j      ) * HID + kk],
                                 Wm[(HID + j) * HID + kk],
                                 Wm[(2*HID+j) * HID + kk],
                                 Wm[(3*HID+j) * HID + kk]);
    }
    for (int j = tid; j < HID; j += bd) {
        s_wx1[j] = make_float4(W_ih1[j], W_ih1[HID + j], W_ih1[2*HID + j], W_ih1[3*HID + j]);
        s_bq1[j] = make_float4(b_ih1[j]       + b_hh1[j],
                               b_ih1[HID+j]   + b_hh1[HID+j],
                               b_ih1[2*HID+j] + b_hh1[2*HID+j],
                               b_ih1[3*HID+j] + b_hh1[3*HID+j]);
        s_bq2[j] = make_float4(b_ih2[j]       + b_hh2[j],
                               b_ih2[HID+j]   + b_hh2[HID+j],
                               b_ih2[2*HID+j] + b_hh2[2*HID+j],
                               b_ih2[3*HID+j] + b_hh2[3*HID+j]);
    }
    for (int i = tid; i < FFD * HID; i += bd) s_W1f[i] = W1[i];
    for (int i = tid; i < FFD; i += bd) { s_b1f[i] = b1[i]; s_W2f[i] = W2[i]; }
    if (tid == 0) s_b2f = b2[0];
    __syncthreads();

    const int b = blockIdx.x * bd + tid;
    if (b >= rows) return;

    float h1[HID], c1[HID], h2[HID], c2[HID];
#pragma unroll
    for (int j = 0; j < HID; j++) { h1[j] = 0.f; c1[j] = 0.f; h2[j] = 0.f; c2[j] = 0.f; }

    const float* __restrict__ xrow = diag + (size_t)b * T_LEN;

#pragma unroll 1
    for (int t = 0; t < T_LEN; t++) {
        const float x = __ldg(xrow + t);
        float h1n[HID], h2n[HID];

        // ---- layer 1: per-j gate-quad accumulation ----
#pragma unroll
        for (int j = 0; j < HID; j++) {
            float4 wx = s_wx1[j];
            float4 bq = s_bq1[j];
            float2 zif = ffma2(make_float2(wx.x, wx.y), make_float2(x, x),
                               make_float2(bq.x, bq.y));
            float2 zgo = ffma2(make_float2(wx.z, wx.w), make_float2(x, x),
                               make_float2(bq.z, bq.w));
#pragma unroll
            for (int k = 0; k < HID; k++) {
                float4 w = s_w1[j][k];
                float2 hh = make_float2(h1[k], h1[k]);
                zif = ffma2(make_float2(w.x, w.y), hh, zif);
                zgo = ffma2(make_float2(w.z, w.w), hh, zgo);
            }
            float ii = sigm(zif.x);
            float ff = sigm(zif.y);
            float gg = tanhap(zgo.x);
            float oo = sigm(zgo.y);
            float cc = fmaf(ff, c1[j], ii * gg);
            c1[j]  = cc;
            h1n[j] = oo * tanhap(cc);
        }
#pragma unroll
        for (int j = 0; j < HID; j++) h1[j] = h1n[j];

        // ---- layer 2 ----
#pragma unroll
        for (int j = 0; j < HID; j++) {
            float4 bq = s_bq2[j];
            float2 zif = make_float2(bq.x, bq.y);
            float2 zgo = make_float2(bq.z, bq.w);
#pragma unroll
            for (int k = 0; k < HID; k++) {
                float4 w = s_w2[j][k];
                float2 hh = make_float2(h1[k], h1[k]);
                zif = ffma2(make_float2(w.x, w.y), hh, zif);
                zgo = ffma2(make_float2(w.z, w.w), hh, zgo);
            }
#pragma unroll
            for (int k = 0; k < HID; k++) {
                float4 w = s_w2[j][HID + k];
                float2 hh = make_float2(h2[k], h2[k]);
                zif = ffma2(make_float2(w.x, w.y), hh, zif);
                zgo = ffma2(make_float2(w.z, w.w), hh, zgo);
            }
            float ii = sigm(zif.x);
            float ff = sigm(zif.y);
            float gg = tanhap(zgo.x);
            float oo = sigm(zgo.y);
            float cc = fmaf(ff, c2[j], ii * gg);
            c2[j]  = cc;
            h2n[j] = oo * tanhap(cc);
        }
#pragma unroll
        for (int j = 0; j < HID; j++) h2[j] = h2n[j];
    }

    // ---- head: relu(relu(h2 @ W1^T + b1) @ W2^T + b2) ----
    float acc2 = s_b2f;
#pragma unroll 1
    for (int n = 0; n < FFD; n++) {
        float a = s_b1f[n];
#pragma unroll
        for (int k = 0; k < HID; k++)
            a = fmaf(s_W1f[n * HID + k], h2[k], a);
        a = fmaxf(a, 0.0f);
        acc2 = fmaf(s_W2f[n], a, acc2);
    }
    out[b] = fmaxf(acc2, 0.0f);
}

extern "C" void kernel_launch(void* const* d_in, const int* in_sizes, int n_in,
                              void* d_out, int out_size) {
    const float* diag  = (const float*)d_in[0];
    const float* W_ih1 = (const float*)d_in[1];
    const float* W_hh1 = (const float*)d_in[2];
    const float* b_ih1 = (const float*)d_in[3];
    const float* b_hh1 = (const float*)d_in[4];
    const float* W_ih2 = (const float*)d_in[5];
    const float* W_hh2 = (const float*)d_in[6];
    const float* b_ih2 = (const float*)d_in[7];
    const float* b_hh2 = (const float*)d_in[8];
    const float* W1    = (const float*)d_in[9];
    const float* b1    = (const float*)d_in[10];
    const float* W2    = (const float*)d_in[11];
    const float* b2    = (const float*)d_in[12];

    int rows = out_size;  // B = 131072
    int threads = 128;
    int blocks = (rows + threads - 1) / threads;

    lstm2_head_kernel<<<blocks, threads>>>(
        diag, W_ih1, W_hh1, b_ih1, b_hh1,
        W_ih2, W_hh2, b_ih2, b_hh2,
        W1, b1, W2, b2, (float*)d_out, rows);
}

// round 3
// speedup vs baseline: 1.2644x; 1.1768x over previous
#include <cuda_runtime.h>

#define T_LEN 256
#define HID   20
#define FFD   64

// ---------- packed fp32x2 FMA (sm_103a; PTX-only path) ----------
union F2U { float2 f; unsigned long long u; };

__device__ __forceinline__ float2 ffma2(float2 a, float2 b, float2 c) {
    F2U A, B, C, D;
    A.f = a; B.f = b; C.f = c;
    asm("fma.rn.f32x2 %0, %1, %2, %3;" : "=l"(D.u) : "l"(A.u), "l"(B.u), "l"(C.u));
    return D.f;
}

__device__ __forceinline__ float tanhap(float x) {
    float r; asm("tanh.approx.f32 %0, %1;" : "=f"(r) : "f"(x)); return r;
}
// sigmoid(x) = 0.5 * tanh(x/2) + 0.5
__device__ __forceinline__ float sigm(float x) {
    return fmaf(0.5f, tanhap(0.5f * x), 0.5f);
}

__global__ void __launch_bounds__(128, 2) lstm2_head_kernel(
    const float* __restrict__ diag,
    const float* __restrict__ W_ih1, const float* __restrict__ W_hh1,
    const float* __restrict__ b_ih1, const float* __restrict__ b_hh1,
    const float* __restrict__ W_ih2, const float* __restrict__ W_hh2,
    const float* __restrict__ b_ih2, const float* __restrict__ b_hh2,
    const float* __restrict__ W1,   const float* __restrict__ b1,
    const float* __restrict__ W2,   const float* __restrict__ b2,
    float* __restrict__ out, int rows)
{
    // Gate-quad weight layout: s_w[j][k] = (Wi[j][k], Wf[j][k], Wg[j][k], Wo[j][k])
    __shared__ float4 s_w1[HID][HID];       // layer1 recurrent  (6.4 KB)
    __shared__ float4 s_w2[HID][2 * HID];   // layer2 [h1new | h2old] (12.8 KB)
    __shared__ float4 s_wx1[HID];           // layer1 input weights (in_dim=1)
    __shared__ float4 s_bq1[HID];           // summed biases, quad layout
    __shared__ float4 s_bq2[HID];
    __shared__ float  s_W1f[FFD * HID];
    __shared__ float  s_b1f[FFD];
    __shared__ float  s_W2f[FFD];
    __shared__ float  s_b2f;

    const int tid = threadIdx.x;
    const int bd  = blockDim.x;

    for (int idx = tid; idx < HID * HID; idx += bd) {
        int j = idx / HID, k = idx % HID;
        s_w1[j][k] = make_float4(W_hh1[(j      ) * HID + k],
                                 W_hh1[(HID + j) * HID + k],
                                 W_hh1[(2*HID+j) * HID + k],
                                 W_hh1[(3*HID+j) * HID + k]);
    }
    for (int idx = tid; idx < HID * 2 * HID; idx += bd) {
        int j = idx / (2 * HID), k = idx % (2 * HID);
        const float* Wm = (k < HID) ? W_ih2 : W_hh2;
        int kk = (k < HID) ? k : (k - HID);
        s_w2[j][k] = make_float4(Wm[(j      ) * HID + kk],
                                 Wm[(HID + j) * HID + kk],
                                 Wm[(2*HID+j) * HID + kk],
                                 Wm[(3*HID+j) * HID + kk]);
    }
    for (int j = tid; j < HID; j += bd) {
        s_wx1[j] = make_float4(W_ih1[j], W_ih1[HID + j], W_ih1[2*HID + j], W_ih1[3*HID + j]);
        s_bq1[j] = make_float4(b_ih1[j]       + b_hh1[j],
                               b_ih1[HID+j]   + b_hh1[HID+j],
                               b_ih1[2*HID+j] + b_hh1[2*HID+j],
                               b_ih1[3*HID+j] + b_hh1[3*HID+j]);
        s_bq2[j] = make_float4(b_ih2[j]       + b_hh2[j],
                               b_ih2[HID+j]   + b_hh2[HID+j],
                               b_ih2[2*HID+j] + b_hh2[2*HID+j],
                               b_ih2[3*HID+j] + b_hh2[3*HID+j]);
    }
    for (int i = tid; i < FFD * HID; i += bd) s_W1f[i] = W1[i];
    for (int i = tid; i < FFD; i += bd) { s_b1f[i] = b1[i]; s_W2f[i] = W2[i]; }
    if (tid == 0) s_b2f = b2[0];
    __syncthreads();

    // Two batch rows per thread.
    const int tix = blockIdx.x * bd + tid;
    const int r0 = 2 * tix, r1 = 2 * tix + 1;
    if (r0 >= rows) return;

    float h1[2][HID], c1[2][HID], h2[2][HID], c2[2][HID];
#pragma unroll
    for (int j = 0; j < HID; j++) {
        h1[0][j] = 0.f; c1[0][j] = 0.f; h2[0][j] = 0.f; c2[0][j] = 0.f;
        h1[1][j] = 0.f; c1[1][j] = 0.f; h2[1][j] = 0.f; c2[1][j] = 0.f;
    }

    const float* __restrict__ x0p = diag + (size_t)r0 * T_LEN;
    const float* __restrict__ x1p = diag + (size_t)r1 * T_LEN;

#pragma unroll 1
    for (int t = 0; t < T_LEN; t++) {
        const float x0 = __ldg(x0p + t);
        const float x1 = __ldg(x1p + t);
        float h1n[2][HID], h2n[2][HID];

        // ---- layer 1: per-j gate-quad accumulation, both rows share weights ----
#pragma unroll
        for (int j = 0; j < HID; j++) {
            float4 wx = s_wx1[j];
            float4 bq = s_bq1[j];
            float2 wif = make_float2(wx.x, wx.y), wgo = make_float2(wx.z, wx.w);
            float2 bif = make_float2(bq.x, bq.y), bgo = make_float2(bq.z, bq.w);
            float2 zif0 = ffma2(wif, make_float2(x0, x0), bif);
            float2 zgo0 = ffma2(wgo, make_float2(x0, x0), bgo);
            float2 zif1 = ffma2(wif, make_float2(x1, x1), bif);
            float2 zgo1 = ffma2(wgo, make_float2(x1, x1), bgo);
#pragma unroll
            for (int k = 0; k < HID; k++) {
                float4 w = s_w1[j][k];
                float2 a = make_float2(w.x, w.y), bb = make_float2(w.z, w.w);
                float2 h0 = make_float2(h1[0][k], h1[0][k]);
                float2 hh = make_float2(h1[1][k], h1[1][k]);
                zif0 = ffma2(a, h0, zif0);  zgo0 = ffma2(bb, h0, zgo0);
                zif1 = ffma2(a, hh, zif1);  zgo1 = ffma2(bb, hh, zgo1);
            }
            {
                float ii = sigm(zif0.x), ff = sigm(zif0.y);
                float gg = tanhap(zgo0.x), oo = sigm(zgo0.y);
                float cc = fmaf(ff, c1[0][j], ii * gg);
                c1[0][j] = cc; h1n[0][j] = oo * tanhap(cc);
            }
            {
                float ii = sigm(zif1.x), ff = sigm(zif1.y);
                float gg = tanhap(zgo1.x), oo = sigm(zgo1.y);
                float cc = fmaf(ff, c1[1][j], ii * gg);
                c1[1][j] = cc; h1n[1][j] = oo * tanhap(cc);
            }
        }
#pragma unroll
        for (int j = 0; j < HID; j++) { h1[0][j] = h1n[0][j]; h1[1][j] = h1n[1][j]; }

        // ---- layer 2 ----
#pragma unroll
        for (int j = 0; j < HID; j++) {
            float4 bq = s_bq2[j];
            float2 zif0 = make_float2(bq.x, bq.y), zgo0 = make_float2(bq.z, bq.w);
            float2 zif1 = zif0, zgo1 = zgo0;
#pragma unroll
            for (int k = 0; k < HID; k++) {
                float4 w = s_w2[j][k];
                float2 a = make_float2(w.x, w.y), bb = make_float2(w.z, w.w);
                float2 h0 = make_float2(h1[0][k], h1[0][k]);
                float2 hh = make_float2(h1[1][k], h1[1][k]);
                zif0 = ffma2(a, h0, zif0);  zgo0 = ffma2(bb, h0, zgo0);
                zif1 = ffma2(a, hh, zif1);  zgo1 = ffma2(bb, hh, zgo1);
            }
#pragma unroll
            for (int k = 0; k < HID; k++) {
                float4 w = s_w2[j][HID + k];
                float2 a = make_float2(w.x, w.y), bb = make_float2(w.z, w.w);
                float2 h0 = make_float2(h2[0][k], h2[0][k]);
                float2 hh = make_float2(h2[1][k], h2[1][k]);
                zif0 = ffma2(a, h0, zif0);  zgo0 = ffma2(bb, h0, zgo0);
                zif1 = ffma2(a, hh, zif1);  zgo1 = ffma2(bb, hh, zgo1);
            }
            {
                float ii = sigm(zif0.x), ff = sigm(zif0.y);
                float gg = tanhap(zgo0.x), oo = sigm(zgo0.y);
                float cc = fmaf(ff, c2[0][j], ii * gg);
                c2[0][j] = cc; h2n[0][j] = oo * tanhap(cc);
            }
            {
                float ii = sigm(zif1.x), ff = sigm(zif1.y);
                float gg = tanhap(zgo1.x), oo = sigm(zgo1.y);
                float cc = fmaf(ff, c2[1][j], ii * gg);
                c2[1][j] = cc; h2n[1][j] = oo * tanhap(cc);
            }
        }
#pragma unroll
        for (int j = 0; j < HID; j++) { h2[0][j] = h2n[0][j]; h2[1][j] = h2n[1][j]; }
    }

    // ---- head: relu(relu(h2 @ W1^T + b1) @ W2^T + b2), both rows ----
    float acc0 = s_b2f, acc1 = s_b2f;
#pragma unroll 1
    for (int n = 0; n < FFD; n++) {
        float a0 = s_b1f[n], a1 = s_b1f[n];
#pragma unroll
        for (int k = 0; k < HID; k++) {
            float w = s_W1f[n * HID + k];
            a0 = fmaf(w, h2[0][k], a0);
            a1 = fmaf(w, h2[1][k], a1);
        }
        float w2v = s_W2f[n];
        acc0 = fmaf(w2v, fmaxf(a0, 0.0f), acc0);
        acc1 = fmaf(w2v, fmaxf(a1, 0.0f), acc1);
    }
    out[r0] = fmaxf(acc0, 0.0f);
    if (r1 < rows) out[r1] = fmaxf(acc1, 0.0f);
}

extern "C" void kernel_launch(void* const* d_in, const int* in_sizes, int n_in,
                              void* d_out, int out_size) {
    const float* diag  = (const float*)d_in[0];
    const float* W_ih1 = (const float*)d_in[1];
    const float* W_hh1 = (const float*)d_in[2];
    const float* b_ih1 = (const float*)d_in[3];
    const float* b_hh1 = (const float*)d_in[4];
    const float* W_ih2 = (const float*)d_in[5];
    const float* W_hh2 = (const float*)d_in[6];
    const float* b_ih2 = (const float*)d_in[7];
    const float* b_hh2 = (const float*)d_in[8];
    const float* W1    = (const float*)d_in[9];
    const float* b1    = (const float*)d_in[10];
    const float* W2    = (const float*)d_in[11];
    const float* b2    = (const float*)d_in[12];

    int rows = out_size;              // B = 131072
    int threads = 128;
    int rows_per_block = threads * 2; // 2 rows per thread
    int blocks = (rows + rows_per_block - 1) / rows_per_block;

    lstm2_head_kernel<<<blocks, threads>>>(
        diag, W_ih1, W_hh1, b_ih1, b_hh1,
        W_ih2, W_hh2, b_ih2, b_hh2,
        W1, b1, W2, b2, (float*)d_out, rows);
}